// round 1
// baseline (speedup 1.0000x reference)
#include <cuda_runtime.h>
#include <cstdint>

// Problem constants (fixed shapes for this problem)
#define BATCH 2
#define RDIM  64
#define CDIM  2048
#define EDIM  128
#define HEADS 4
#define DHEAD 32
#define NROWS (BATCH*RDIM*CDIM)      // 262144
#define NBR   (BATCH*RDIM)           // 128

// Scratch (device globals: allocation-free rule)
__device__ float g_q[(size_t)NROWS * EDIM];
__device__ float g_k[(size_t)NROWS * EDIM];
__device__ float g_v[(size_t)NROWS * EDIM];
__device__ float g_ktv[(size_t)NBR * HEADS * DHEAD * DHEAD]; // [br][h][d][e]
__device__ float g_ksum[(size_t)NBR * HEADS * DHEAD];        // [br][h][d]

__device__ __forceinline__ float elu1(float x) {
    return x > 0.f ? x + 1.f : expf(x);
}

// ---------------------------------------------------------------------------
// Kernel A: fused QKV projection. Each block: 64 rows x 128 cols, 3 weights.
// dyn smem: xs[64*128] + ws[128*128] = 96KB
// ---------------------------------------------------------------------------
__global__ __launch_bounds__(256) void qkv_kernel(
    const float* __restrict__ x,
    const float* __restrict__ Wq, const float* __restrict__ bq,
    const float* __restrict__ Wk, const float* __restrict__ bk,
    const float* __restrict__ Wv, const float* __restrict__ bv)
{
    extern __shared__ float sm[];
    float* xs = sm;              // 64*128
    float* ws = sm + 64 * 128;   // 128*128

    const int tid = threadIdx.x;
    const size_t row0 = (size_t)blockIdx.x * 64;

    // load x tile (2048 float4)
    const float4* xg = reinterpret_cast<const float4*>(x + row0 * EDIM);
    float4* xs4 = reinterpret_cast<float4*>(xs);
#pragma unroll
    for (int i = 0; i < 8; ++i) xs4[tid + i * 256] = xg[tid + i * 256];

    const int ty = tid >> 5;   // 0..7 (row group)
    const int tx = tid & 31;   // 0..31 (col group)

    const float* Wlist[3] = {Wq, Wk, Wv};
    const float* Blist[3] = {bq, bk, bv};
    float* Olist[3] = {g_q, g_k, g_v};

    for (int w = 0; w < 3; ++w) {
        __syncthreads();   // xs ready (w==0) / ws safe to overwrite (w>0)
        const float4* wg = reinterpret_cast<const float4*>(Wlist[w]);
        float4* ws4 = reinterpret_cast<float4*>(ws);
#pragma unroll
        for (int i = 0; i < 16; ++i) ws4[tid + i * 256] = wg[tid + i * 256];
        __syncthreads();

        float acc[8][4];
#pragma unroll
        for (int i = 0; i < 8; ++i)
#pragma unroll
            for (int j = 0; j < 4; ++j) acc[i][j] = 0.f;

#pragma unroll 4
        for (int kk = 0; kk < 128; ++kk) {
            float4 b4 = *reinterpret_cast<const float4*>(&ws[kk * 128 + tx * 4]);
#pragma unroll
            for (int i = 0; i < 8; ++i) {
                float a = xs[(ty * 8 + i) * 128 + kk];
                acc[i][0] += a * b4.x;
                acc[i][1] += a * b4.y;
                acc[i][2] += a * b4.z;
                acc[i][3] += a * b4.w;
            }
        }

        float4 bb = *reinterpret_cast<const float4*>(&Blist[w][tx * 4]);
        float* outp = Olist[w];
#pragma unroll
        for (int i = 0; i < 8; ++i) {
            float4 r;
            r.x = acc[i][0] + bb.x;
            r.y = acc[i][1] + bb.y;
            r.z = acc[i][2] + bb.z;
            r.w = acc[i][3] + bb.w;
            if (w < 2) {  // q and k get elu+1 feature map
                r.x = elu1(r.x); r.y = elu1(r.y); r.z = elu1(r.z); r.w = elu1(r.w);
            }
            *reinterpret_cast<float4*>(&outp[(row0 + ty * 8 + i) * EDIM + tx * 4]) = r;
        }
    }
}

// ---------------------------------------------------------------------------
// Kernel B: per (b,r,h): KtV[d][e] = sum_c k[c,d]*v[c,e];  ksum[d] = sum_c k[c,d]
// grid = NBR*HEADS = 512 blocks, 256 threads. Each thread owns d = tid/8,
// e = (tid%8)*4 .. +3.
// ---------------------------------------------------------------------------
__global__ __launch_bounds__(256) void ktv_kernel()
{
    __shared__ float ks[64 * 32];
    __shared__ float vs[64 * 32];

    const int tid = threadIdx.x;
    const int brh = blockIdx.x;   // 0..511
    const int br  = brh >> 2;
    const int h   = brh & 3;
    const size_t base = (size_t)br * CDIM * EDIM + h * DHEAD;

    const int d  = tid >> 3;     // 0..31
    const int j8 = tid & 7;      // 0..7

    float a0 = 0.f, a1 = 0.f, a2 = 0.f, a3 = 0.f, ksum = 0.f;

    for (int c0 = 0; c0 < CDIM; c0 += 64) {
        __syncthreads();
#pragma unroll
        for (int i = 0; i < 2; ++i) {
            int idx = tid + i * 256;      // 0..511
            int c  = idx >> 3;
            int jj = idx & 7;
            const float4* kg = reinterpret_cast<const float4*>(g_k + base + (size_t)(c0 + c) * EDIM) + jj;
            reinterpret_cast<float4*>(ks)[c * 8 + jj] = *kg;
            const float4* vg = reinterpret_cast<const float4*>(g_v + base + (size_t)(c0 + c) * EDIM) + jj;
            reinterpret_cast<float4*>(vs)[c * 8 + jj] = *vg;
        }
        __syncthreads();
#pragma unroll 8
        for (int c = 0; c < 64; ++c) {
            float kd = ks[c * 32 + d];
            float4 vv = reinterpret_cast<const float4*>(vs)[c * 8 + j8];
            a0 += kd * vv.x;
            a1 += kd * vv.y;
            a2 += kd * vv.z;
            a3 += kd * vv.w;
            ksum += kd;
        }
    }

    float4 r; r.x = a0; r.y = a1; r.z = a2; r.w = a3;
    reinterpret_cast<float4*>(g_ktv)[(size_t)brh * 256 + d * 8 + j8] = r;
    if (j8 == 0) g_ksum[(size_t)brh * 32 + d] = ksum;
}

// ---------------------------------------------------------------------------
// Kernel C: per 64-row tile of one (b,r):
//   z = 1/(q . ksum + eps); attn = (q @ KtV) * z; out = attn @ Wo + bo
// dyn smem: qs[8192] + attn[8192] + ws[16384] + ktv[4096] + ksum[128] + z[256]
//         = 37248 floats = 148992 B
// ---------------------------------------------------------------------------
__global__ __launch_bounds__(256) void out_kernel(
    const float* __restrict__ Wo, const float* __restrict__ bo,
    float* __restrict__ out)
{
    extern __shared__ float sm[];
    float* qs    = sm;            // 8192
    float* as_   = sm + 8192;     // 8192
    float* ws    = sm + 16384;    // 16384
    float* ktvs  = sm + 32768;    // 4096
    float* ksums = sm + 36864;    // 128
    float* zs    = sm + 36992;    // 256

    const int tid = threadIdx.x;
    const int bx  = blockIdx.x;
    const int br  = bx >> 5;           // CDIM/64 = 32 tiles per (b,r)
    const int ct  = bx & 31;
    const size_t row0 = (size_t)br * CDIM + ct * 64;

    // loads
    const float4* qg = reinterpret_cast<const float4*>(g_q + row0 * EDIM);
    float4* qs4 = reinterpret_cast<float4*>(qs);
#pragma unroll
    for (int i = 0; i < 8; ++i) qs4[tid + i * 256] = qg[tid + i * 256];

    const float4* wg = reinterpret_cast<const float4*>(Wo);
    float4* ws4 = reinterpret_cast<float4*>(ws);
#pragma unroll
    for (int i = 0; i < 16; ++i) ws4[tid + i * 256] = wg[tid + i * 256];

    const float4* kg = reinterpret_cast<const float4*>(g_ktv + (size_t)br * 4096);
    float4* kt4 = reinterpret_cast<float4*>(ktvs);
#pragma unroll
    for (int i = 0; i < 4; ++i) kt4[tid + i * 256] = kg[tid + i * 256];

    if (tid < 32)
        reinterpret_cast<float4*>(ksums)[tid] =
            reinterpret_cast<const float4*>(g_ksum + (size_t)br * 128)[tid];

    __syncthreads();

    // normalizer z: one (row, head) per thread
    {
        int row = tid >> 2;
        int h   = tid & 3;
        const float* qp = &qs[row * 128 + h * 32];
        const float* kp = &ksums[h * 32];
        float dot = 0.f;
#pragma unroll
        for (int dd = 0; dd < 32; ++dd) dot += qp[dd] * kp[dd];
        zs[row * 4 + h] = 1.f / (dot + 1e-6f);
    }
    __syncthreads();

    const int ty = tid >> 5;
    const int tx = tid & 31;
    const int h  = tx >> 3;       // head for this col group (cols tx*4..+3)

    // attn = (q @ KtV) * z
    {
        float acc[8][4];
#pragma unroll
        for (int i = 0; i < 8; ++i)
#pragma unroll
            for (int j = 0; j < 4; ++j) acc[i][j] = 0.f;

#pragma unroll 4
        for (int dd = 0; dd < 32; ++dd) {
            float4 b4 = *reinterpret_cast<const float4*>(
                &ktvs[h * 1024 + dd * 32 + (tx & 7) * 4]);
#pragma unroll
            for (int i = 0; i < 8; ++i) {
                float a = qs[(ty * 8 + i) * 128 + h * 32 + dd];
                acc[i][0] += a * b4.x;
                acc[i][1] += a * b4.y;
                acc[i][2] += a * b4.z;
                acc[i][3] += a * b4.w;
            }
        }
#pragma unroll
        for (int i = 0; i < 8; ++i) {
            float z = zs[(ty * 8 + i) * 4 + h];
            float4 r;
            r.x = acc[i][0] * z; r.y = acc[i][1] * z;
            r.z = acc[i][2] * z; r.w = acc[i][3] * z;
            *reinterpret_cast<float4*>(&as_[(ty * 8 + i) * 128 + tx * 4]) = r;
        }
    }
    __syncthreads();

    // out = attn @ Wo + bo
    {
        float acc[8][4];
#pragma unroll
        for (int i = 0; i < 8; ++i)
#pragma unroll
            for (int j = 0; j < 4; ++j) acc[i][j] = 0.f;

#pragma unroll 4
        for (int kk = 0; kk < 128; ++kk) {
            float4 b4 = *reinterpret_cast<const float4*>(&ws[kk * 128 + tx * 4]);
#pragma unroll
            for (int i = 0; i < 8; ++i) {
                float a = as_[(ty * 8 + i) * 128 + kk];
                acc[i][0] += a * b4.x;
                acc[i][1] += a * b4.y;
                acc[i][2] += a * b4.z;
                acc[i][3] += a * b4.w;
            }
        }
        float4 bb = *reinterpret_cast<const float4*>(&bo[tx * 4]);
#pragma unroll
        for (int i = 0; i < 8; ++i) {
            float4 r;
            r.x = acc[i][0] + bb.x; r.y = acc[i][1] + bb.y;
            r.z = acc[i][2] + bb.z; r.w = acc[i][3] + bb.w;
            *reinterpret_cast<float4*>(&out[(row0 + ty * 8 + i) * EDIM + tx * 4]) = r;
        }
    }
}

// ---------------------------------------------------------------------------
extern "C" void kernel_launch(void* const* d_in, const int* in_sizes, int n_in,
                              void* d_out, int out_size)
{
    const float* x  = (const float*)d_in[0];
    const float* Wq = (const float*)d_in[1];
    const float* bq = (const float*)d_in[2];
    const float* Wk = (const float*)d_in[3];
    const float* bk = (const float*)d_in[4];
    const float* Wv = (const float*)d_in[5];
    const float* bv = (const float*)d_in[6];
    const float* Wo = (const float*)d_in[7];
    const float* bo = (const float*)d_in[8];
    float* out = (float*)d_out;

    const int smemA = (64 * 128 + 128 * 128) * 4;   // 96 KB
    const int smemC = 37248 * 4;                    // ~145.5 KB

    cudaFuncSetAttribute(qkv_kernel, cudaFuncAttributeMaxDynamicSharedMemorySize, smemA);
    cudaFuncSetAttribute(out_kernel, cudaFuncAttributeMaxDynamicSharedMemorySize, smemC);

    qkv_kernel<<<NROWS / 64, 256, smemA>>>(x, Wq, bq, Wk, bk, Wv, bv);
    ktv_kernel<<<NBR * HEADS, 256>>>();
    out_kernel<<<NROWS / 64, 256, smemC>>>(Wo, bo, out);
}